// round 8
// baseline (speedup 1.0000x reference)
#include <cuda_runtime.h>
#include <math.h>

#define NN 384
#define CC 128
#define HH 4
#define DD 32
#define MM (NN*NN)

// Scratch (allocation-free: __device__ globals)
__device__ float d_x[(size_t)MM*CC];      // layernormed pair
__device__ float d_y[(size_t)MM*512];     // [q|k|v|g] concatenated, q pre-scaled
__device__ float d_bias[(size_t)HH*MM];   // bias[h, q, k]
__device__ float d_o[(size_t)MM*CC];      // attention output [b,n,h*32+d]

// ---- tf32 tensor-core helpers ----
__device__ __forceinline__ unsigned cvt_tf32(float f) {
    unsigned u;
    asm("cvt.rna.tf32.f32 %0, %1;" : "=r"(u) : "f"(f));
    return u;
}
__device__ __forceinline__ void mma_tf32(float& c0, float& c1, float& c2, float& c3,
                                         unsigned a0, unsigned a1, unsigned a2, unsigned a3,
                                         unsigned b0, unsigned b1) {
    asm("mma.sync.aligned.m16n8k8.row.col.f32.tf32.tf32.f32 "
        "{%0,%1,%2,%3}, {%4,%5,%6,%7}, {%8,%9}, {%0,%1,%2,%3};"
        : "+f"(c0), "+f"(c1), "+f"(c2), "+f"(c3)
        : "r"(a0), "r"(a1), "r"(a2), "r"(a3), "r"(b0), "r"(b1));
}

// ---------------------------------------------------------------------------
// Kernel 1: LayerNorm + pair bias. One warp per row (128 channels, 4/lane).
// ---------------------------------------------------------------------------
__global__ __launch_bounds__(256) void ln_bias_kernel(
    const float* __restrict__ pair,
    const float* __restrict__ ln_w,
    const float* __restrict__ ln_b,
    const float* __restrict__ w_bias)
{
    int warp = threadIdx.x >> 5, lane = threadIdx.x & 31;
    int r = blockIdx.x * 8 + warp;
    if (r >= MM) return;

    float4 v = ((const float4*)(pair + (size_t)r * CC))[lane];
    float s  = v.x + v.y + v.z + v.w;
    float sq = v.x*v.x + v.y*v.y + v.z*v.z + v.w*v.w;
    #pragma unroll
    for (int o = 16; o; o >>= 1) {
        s  += __shfl_xor_sync(0xffffffffu, s,  o);
        sq += __shfl_xor_sync(0xffffffffu, sq, o);
    }
    float mean = s * (1.0f / CC);
    float var  = sq * (1.0f / CC) - mean * mean;
    float inv  = rsqrtf(var + 1e-5f);

    float4 w = ((const float4*)ln_w)[lane];
    float4 b = ((const float4*)ln_b)[lane];
    float4 xn;
    xn.x = (v.x - mean) * inv * w.x + b.x;
    xn.y = (v.y - mean) * inv * w.y + b.y;
    xn.z = (v.z - mean) * inv * w.z + b.z;
    xn.w = (v.w - mean) * inv * w.w + b.w;
    ((float4*)(d_x + (size_t)r * CC))[lane] = xn;

    float accb0 = 0.f, accb1 = 0.f, accb2 = 0.f, accb3 = 0.f;
    float xv[4] = {xn.x, xn.y, xn.z, xn.w};
    #pragma unroll
    for (int i = 0; i < 4; i++) {
        float4 wb = ((const float4*)w_bias)[lane * 4 + i];
        accb0 += xv[i] * wb.x;
        accb1 += xv[i] * wb.y;
        accb2 += xv[i] * wb.z;
        accb3 += xv[i] * wb.w;
    }
    #pragma unroll
    for (int o = 16; o; o >>= 1) {
        accb0 += __shfl_xor_sync(0xffffffffu, accb0, o);
        accb1 += __shfl_xor_sync(0xffffffffu, accb1, o);
        accb2 += __shfl_xor_sync(0xffffffffu, accb2, o);
        accb3 += __shfl_xor_sync(0xffffffffu, accb3, o);
    }
    if (lane == 0) {
        d_bias[(size_t)0 * MM + r] = accb0;
        d_bias[(size_t)1 * MM + r] = accb1;
        d_bias[(size_t)2 * MM + r] = accb2;
        d_bias[(size_t)3 * MM + r] = accb3;
    }
}

// ---------------------------------------------------------------------------
// Kernel 2: projections Y[M,512] = X[M,128] @ [wq|wk|wv|wg] on tensor cores.
// Block = 64 rows x ALL 512 cols: X staged ONCE (no redundant DRAM re-reads),
// W streamed per 64-col group straight into [k][n] layout (no transpose).
// 256 threads / 8 warps: warp = m16 tile (w&3) x 4 n8 blocks (w>>2).
// A-fragments persist in registers across all 8 groups.
// ---------------------------------------------------------------------------
__global__ __launch_bounds__(256) void proj_gemm_tc(
    const float* __restrict__ wq, const float* __restrict__ wk,
    const float* __restrict__ wv, const float* __restrict__ wg)
{
    __shared__ float Xs[64][132];    // 33792 B ; A-frag bank = 4g+t (distinct)
    __shared__ float Ws[128][72];    // 36864 B ; B-frag bank = 8t+8nb+g (distinct)

    int m0 = blockIdx.x * 64;
    int tid = threadIdx.x, lane = tid & 31, warp = tid >> 5;
    int g = lane >> 2, t = lane & 3;
    int mt = warp & 3;               // m16 tile within 64 rows
    int npair = warp >> 2;           // 0..1 -> n8 blocks npair*4 .. +3

    // Stage X tile once (tf32-rounded), float4 in/out
    for (int i = tid; i < 64 * 32; i += 256) {
        int row = i >> 5, c4 = (i & 31) * 4;
        float4 v = *(const float4*)&d_x[(size_t)(m0 + row) * 128 + c4];
        float4 o;
        o.x = __uint_as_float(cvt_tf32(v.x));
        o.y = __uint_as_float(cvt_tf32(v.y));
        o.z = __uint_as_float(cvt_tf32(v.z));
        o.w = __uint_as_float(cvt_tf32(v.w));
        *(float4*)&Xs[row][c4] = o;
    }
    __syncthreads();

    // Persistent A-fragments: 16 k8-steps x 4 regs
    unsigned aA[16][4];
    #pragma unroll
    for (int k8 = 0; k8 < 16; k8++) {
        aA[k8][0] = __float_as_uint(Xs[mt * 16 + g][k8 * 8 + t]);
        aA[k8][1] = __float_as_uint(Xs[mt * 16 + g + 8][k8 * 8 + t]);
        aA[k8][2] = __float_as_uint(Xs[mt * 16 + g][k8 * 8 + t + 4]);
        aA[k8][3] = __float_as_uint(Xs[mt * 16 + g + 8][k8 * 8 + t + 4]);
    }

    for (int grp = 0; grp < 8; grp++) {
        int jb = grp * 64;
        int sel = jb >> 7;
        const float* w = (sel == 0) ? wq : (sel == 1) ? wk : (sel == 2) ? wv : wg;
        int jbase = jb & 127;

        __syncthreads();   // previous group's compute done before Ws overwrite
        // Stage W[k][n] slice (already B-layout; float4, no transpose)
        for (int i = tid; i < 128 * 16; i += 256) {
            int k = i >> 4, c4 = (i & 15) * 4;
            float4 v = *(const float4*)&w[(size_t)k * 128 + jbase + c4];
            float4 o;
            o.x = __uint_as_float(cvt_tf32(v.x));
            o.y = __uint_as_float(cvt_tf32(v.y));
            o.z = __uint_as_float(cvt_tf32(v.z));
            o.w = __uint_as_float(cvt_tf32(v.w));
            *(float4*)&Ws[k][c4] = o;
        }
        __syncthreads();

        float c[4][4];
        #pragma unroll
        for (int nb = 0; nb < 4; nb++)
            #pragma unroll
            for (int j = 0; j < 4; j++) c[nb][j] = 0.f;

        #pragma unroll
        for (int k8 = 0; k8 < 16; k8++) {
            #pragma unroll
            for (int nb = 0; nb < 4; nb++) {
                int ncol = (npair * 4 + nb) * 8 + g;
                unsigned b0 = __float_as_uint(Ws[k8 * 8 + t][ncol]);
                unsigned b1 = __float_as_uint(Ws[k8 * 8 + t + 4][ncol]);
                mma_tf32(c[nb][0], c[nb][1], c[nb][2], c[nb][3],
                         aA[k8][0], aA[k8][1], aA[k8][2], aA[k8][3], b0, b1);
            }
        }

        float scale = (sel == 0) ? 0.17677669529663687f : 1.0f;
        #pragma unroll
        for (int nb = 0; nb < 4; nb++) {
            int col = jb + (npair * 4 + nb) * 8 + 2 * t;
            *(float2*)&d_y[(size_t)(m0 + mt * 16 + g) * 512 + col] =
                make_float2(c[nb][0] * scale, c[nb][1] * scale);
            *(float2*)&d_y[(size_t)(m0 + mt * 16 + g + 8) * 512 + col] =
                make_float2(c[nb][2] * scale, c[nb][3] * scale);
        }
    }
}

// ---------------------------------------------------------------------------
// Kernel 3: attention per (b,h), register-resident flash (tf32 mma.sync).
// 256 threads = 8 warps; warp owns 3 m16 q-tiles (mt = w, w+8, w+16).
// ---------------------------------------------------------------------------
#define KT_STRIDE 392
#define VS_STRIDE 40
#define SM_KT   0                         // [32][392] = 12544
#define SM_VS   12544                     // [384][40] = 15360
#define SM_AM   27904                     // [384]
#define ATTN_SMEM_FLOATS 28288            // 113,152 B

__global__ __launch_bounds__(256) void attn_kernel(const int* __restrict__ mask)
{
    extern __shared__ float sm[];
    float* Kt = sm + SM_KT;     // Kt[d][key], tf32 bit patterns
    float* Vs = sm + SM_VS;     // Vs[key][d], tf32 bit patterns
    float* Am = sm + SM_AM;     // additive mask (0 or -1e9)

    int b = blockIdx.x, h = blockIdx.y;
    int tid = threadIdx.x, lane = tid & 31, w = tid >> 5;
    int g = lane >> 2, t = lane & 3;
    const float* Yb = d_y + (size_t)b * (NN * 512);

    for (int idx = tid; idx < NN * 32; idx += 256) {
        int key = idx >> 5, d = idx & 31;
        Kt[d * KT_STRIDE + key] =
            __uint_as_float(cvt_tf32(Yb[(size_t)key * 512 + 128 + h * 32 + d]));
        Vs[key * VS_STRIDE + d] =
            __uint_as_float(cvt_tf32(Yb[(size_t)key * 512 + 256 + h * 32 + d]));
    }
    for (int k = tid; k < NN; k += 256)
        Am[k] = (mask[(size_t)b * NN + k] != 0) ? 0.f : -1e9f;
    __syncthreads();

    int src1 = (lane & ~3) | (t >> 1);
    int src2 = src1 + 2;
    bool odd = (t & 1);

    for (int mt = w; mt < 24; mt += 8) {
        int q0 = mt * 16;

        unsigned aq[4][4];
        #pragma unroll
        for (int s = 0; s < 4; s++) {
            const float* qp = Yb + (size_t)q0 * 512 + h * 32 + s * 8 + t;
            aq[s][0] = cvt_tf32(qp[(size_t)g * 512]);
            aq[s][1] = cvt_tf32(qp[(size_t)(g + 8) * 512]);
            aq[s][2] = cvt_tf32(qp[(size_t)g * 512 + 4]);
            aq[s][3] = cvt_tf32(qp[(size_t)(g + 8) * 512 + 4]);
        }

        float oc[4][4];
        #pragma unroll
        for (int dn = 0; dn < 4; dn++)
            #pragma unroll
            for (int j = 0; j < 4; j++) oc[dn][j] = 0.f;
        float sum_lo = 0.f, sum_hi = 0.f;

        const float* br_lo = d_bias + (size_t)h * MM + (size_t)(q0 + g) * NN;
        const float* br_hi = br_lo + (size_t)8 * NN;

        for (int kb = 0; kb < 6; kb++) {
            float pc[8][4];

            #pragma unroll
            for (int nb = 0; nb < 8; nb++) {
                int k8 = kb * 64 + nb * 8;
                float c0 = 0.f, c1 = 0.f, c2 = 0.f, c3 = 0.f;
                #pragma unroll
                for (int s = 0; s < 4; s++) {
                    unsigned b0 = __float_as_uint(Kt[(s * 8 + t) * KT_STRIDE + k8 + g]);
                    unsigned b1 = __float_as_uint(Kt[(s * 8 + t + 4) * KT_STRIDE + k8 + g]);
                    mma_tf32(c0, c1, c2, c3,
                             aq[s][0], aq[s][1], aq[s][2], aq[s][3], b0, b1);
                }
                int col = k8 + 2 * t;
                float2 blo = *(const float2*)&br_lo[col];
                float2 bhi = *(const float2*)&br_hi[col];
                float2 am  = *(const float2*)&Am[col];
                float e0 = __expf(c0 + blo.x + am.x);
                float e1 = __expf(c1 + blo.y + am.y);
                float e2 = __expf(c2 + bhi.x + am.x);
                float e3 = __expf(c3 + bhi.y + am.y);
                sum_lo += e0 + e1;
                sum_hi += e2 + e3;
                pc[nb][0] = e0; pc[nb][1] = e1; pc[nb][2] = e2; pc[nb][3] = e3;
            }

            #pragma unroll
            for (int j = 0; j < 8; j++) {
                float x0 = __shfl_sync(0xffffffffu, pc[j][0], src1);
                float x1 = __shfl_sync(0xffffffffu, pc[j][1], src1);
                float x2 = __shfl_sync(0xffffffffu, pc[j][2], src1);
                float x3 = __shfl_sync(0xffffffffu, pc[j][3], src1);
                float y0 = __shfl_sync(0xffffffffu, pc[j][0], src2);
                float y1 = __shfl_sync(0xffffffffu, pc[j][1], src2);
                float y2 = __shfl_sync(0xffffffffu, pc[j][2], src2);
                float y3 = __shfl_sync(0xffffffffu, pc[j][3], src2);
                unsigned a0 = cvt_tf32(odd ? x1 : x0);
                unsigned a1 = cvt_tf32(odd ? x3 : x2);
                unsigned a2 = cvt_tf32(odd ? y1 : y0);
                unsigned a3 = cvt_tf32(odd ? y3 : y2);
                int kg = kb * 64 + j * 8;
                #pragma unroll
                for (int dn = 0; dn < 4; dn++) {
                    unsigned b0 = __float_as_uint(Vs[(kg + t) * VS_STRIDE + dn * 8 + g]);
                    unsigned b1 = __float_as_uint(Vs[(kg + t + 4) * VS_STRIDE + dn * 8 + g]);
                    mma_tf32(oc[dn][0], oc[dn][1], oc[dn][2], oc[dn][3],
                             a0, a1, a2, a3, b0, b1);
                }
            }
        }

        #pragma unroll
        for (int o = 1; o <= 2; o <<= 1) {
            sum_lo += __shfl_xor_sync(0xffffffffu, sum_lo, o);
            sum_hi += __shfl_xor_sync(0xffffffffu, sum_hi, o);
        }
        float inv_lo = 1.f / sum_lo;
        float inv_hi = 1.f / sum_hi;

        float* ob = d_o + ((size_t)b * NN + q0) * CC + h * 32;
        #pragma unroll
        for (int dn = 0; dn < 4; dn++) {
            *(float2*)&ob[(size_t)g * CC + dn * 8 + 2 * t] =
                make_float2(oc[dn][0] * inv_lo, oc[dn][1] * inv_lo);
            *(float2*)&ob[(size_t)(g + 8) * CC + dn * 8 + 2 * t] =
                make_float2(oc[dn][2] * inv_hi, oc[dn][3] * inv_hi);
        }
    }
}

// ---------------------------------------------------------------------------
// Kernel 4: out = (o * sigmoid(g)) @ wo. Scalar FFMA (fp32 keeps rel_err margin).
// ---------------------------------------------------------------------------
__global__ __launch_bounds__(256) void out_gemm(
    const float* __restrict__ wo, float* __restrict__ out)
{
    __shared__ float As[64][64];
    __shared__ float Bs[64][64];

    int m0 = blockIdx.x * 64;
    int n0 = blockIdx.y * 64;
    int tx = threadIdx.x & 15, ty = threadIdx.x >> 4;
    float acc[4][4] = {};

    for (int kk = 0; kk < 128; kk += 64) {
        #pragma unroll
        for (int i = 0; i < 4; i++) {
            int idx = threadIdx.x + i * 256;
            int row = idx >> 4, c4 = (idx & 15) * 4;
            float4 ov = *(const float4*)&d_o[(size_t)(m0 + row) * 128 + kk + c4];
            float4 gv = *(const float4*)&d_y[(size_t)(m0 + row) * 512 + 384 + kk + c4];
            float4 a;
            a.x = ov.x * (1.f / (1.f + __expf(-gv.x)));
            a.y = ov.y * (1.f / (1.f + __expf(-gv.y)));
            a.z = ov.z * (1.f / (1.f + __expf(-gv.z)));
            a.w = ov.w * (1.f / (1.f + __expf(-gv.w)));
            *(float4*)&As[row][c4] = a;
            *(float4*)&Bs[row][c4] =
                *(const float4*)&wo[(size_t)(kk + row) * 128 + n0 + c4];
        }
        __syncthreads();
        #pragma unroll 8
        for (int k = 0; k < 64; k++) {
            float4 b4 = *(float4*)&Bs[k][tx * 4];
            float a0 = As[ty*4+0][k], a1 = As[ty*4+1][k];
            float a2 = As[ty*4+2][k], a3 = As[ty*4+3][k];
            acc[0][0] += a0*b4.x; acc[0][1] += a0*b4.y; acc[0][2] += a0*b4.z; acc[0][3] += a0*b4.w;
            acc[1][0] += a1*b4.x; acc[1][1] += a1*b4.y; acc[1][2] += a1*b4.z; acc[1][3] += a1*b4.w;
            acc[2][0] += a2*b4.x; acc[2][1] += a2*b4.y; acc[2][2] += a2*b4.z; acc[2][3] += a2*b4.w;
            acc[3][0] += a3*b4.x; acc[3][1] += a3*b4.y; acc[3][2] += a3*b4.z; acc[3][3] += a3*b4.w;
        }
        __syncthreads();
    }

    #pragma unroll
    for (int i = 0; i < 4; i++) {
        float4 r;
        r.x = acc[i][0]; r.y = acc[i][1]; r.z = acc[i][2]; r.w = acc[i][3];
        *(float4*)&out[(size_t)(m0 + ty*4 + i) * 128 + n0 + tx*4] = r;
    }
}

// ---------------------------------------------------------------------------
extern "C" void kernel_launch(void* const* d_in, const int* in_sizes, int n_in,
                              void* d_out, int out_size)
{
    const float* pair   = (const float*)d_in[0];
    const int*   mask   = (const int*)d_in[1];
    const float* ln_w   = (const float*)d_in[2];
    const float* ln_b   = (const float*)d_in[3];
    const float* w_bias = (const float*)d_in[4];
    const float* wq     = (const float*)d_in[5];
    const float* wk     = (const float*)d_in[6];
    const float* wv     = (const float*)d_in[7];
    const float* wg     = (const float*)d_in[8];
    const float* wo     = (const float*)d_in[9];
    float* out = (float*)d_out;

    (void)in_sizes; (void)n_in; (void)out_size;

    ln_bias_kernel<<<MM / 8, 256>>>(pair, ln_w, ln_b, w_bias);
    proj_gemm_tc<<<MM / 64, 256>>>(wq, wk, wv, wg);

    size_t attn_smem = (size_t)ATTN_SMEM_FLOATS * sizeof(float);
    cudaFuncSetAttribute(attn_kernel,
                         cudaFuncAttributeMaxDynamicSharedMemorySize,
                         (int)attn_smem);
    attn_kernel<<<dim3(NN, HH), 256, attn_smem>>>(mask);

    out_gemm<<<dim3(MM / 64, 2), 256>>>(wo, out);
}

// round 10
// speedup vs baseline: 1.5743x; 1.5743x over previous
#include <cuda_runtime.h>
#include <math.h>
#include <stdint.h>

#define NN 384
#define CC 128
#define HH 4
#define MM (NN*NN)

// Scratch (allocation-free: __device__ globals)
__device__ float d_x[(size_t)MM*CC];      // layernormed pair
__device__ float d_y[(size_t)MM*512];     // [q|k|v|g] concatenated, q pre-scaled
__device__ float d_bias[(size_t)HH*MM];   // bias[h, q, k]
__device__ float d_o[(size_t)MM*CC];      // attention output [b,n,h*32+d]

// ---- tf32 tensor-core helpers ----
__device__ __forceinline__ unsigned cvt_tf32(float f) {
    unsigned u;
    asm("cvt.rna.tf32.f32 %0, %1;" : "=r"(u) : "f"(f));
    return u;
}
__device__ __forceinline__ void mma_tf32(float& c0, float& c1, float& c2, float& c3,
                                         unsigned a0, unsigned a1, unsigned a2, unsigned a3,
                                         unsigned b0, unsigned b1) {
    asm("mma.sync.aligned.m16n8k8.row.col.f32.tf32.tf32.f32 "
        "{%0,%1,%2,%3}, {%4,%5,%6,%7}, {%8,%9}, {%0,%1,%2,%3};"
        : "+f"(c0), "+f"(c1), "+f"(c2), "+f"(c3)
        : "r"(a0), "r"(a1), "r"(a2), "r"(a3), "r"(b0), "r"(b1));
}

// ---------------------------------------------------------------------------
// Kernel 1: LayerNorm + pair bias. One warp per row (128 channels, 4/lane).
// ---------------------------------------------------------------------------
__global__ __launch_bounds__(256) void ln_bias_kernel(
    const float* __restrict__ pair,
    const float* __restrict__ ln_w,
    const float* __restrict__ ln_b,
    const float* __restrict__ w_bias)
{
    int warp = threadIdx.x >> 5, lane = threadIdx.x & 31;
    int r = blockIdx.x * 8 + warp;
    if (r >= MM) return;

    float4 v = ((const float4*)(pair + (size_t)r * CC))[lane];
    float s  = v.x + v.y + v.z + v.w;
    float sq = v.x*v.x + v.y*v.y + v.z*v.z + v.w*v.w;
    #pragma unroll
    for (int o = 16; o; o >>= 1) {
        s  += __shfl_xor_sync(0xffffffffu, s,  o);
        sq += __shfl_xor_sync(0xffffffffu, sq, o);
    }
    float mean = s * (1.0f / CC);
    float var  = sq * (1.0f / CC) - mean * mean;
    float inv  = rsqrtf(var + 1e-5f);

    float4 w = ((const float4*)ln_w)[lane];
    float4 b = ((const float4*)ln_b)[lane];
    float4 xn;
    xn.x = (v.x - mean) * inv * w.x + b.x;
    xn.y = (v.y - mean) * inv * w.y + b.y;
    xn.z = (v.z - mean) * inv * w.z + b.z;
    xn.w = (v.w - mean) * inv * w.w + b.w;
    ((float4*)(d_x + (size_t)r * CC))[lane] = xn;

    float accb0 = 0.f, accb1 = 0.f, accb2 = 0.f, accb3 = 0.f;
    float xv[4] = {xn.x, xn.y, xn.z, xn.w};
    #pragma unroll
    for (int i = 0; i < 4; i++) {
        float4 wb = ((const float4*)w_bias)[lane * 4 + i];
        accb0 += xv[i] * wb.x;
        accb1 += xv[i] * wb.y;
        accb2 += xv[i] * wb.z;
        accb3 += xv[i] * wb.w;
    }
    #pragma unroll
    for (int o = 16; o; o >>= 1) {
        accb0 += __shfl_xor_sync(0xffffffffu, accb0, o);
        accb1 += __shfl_xor_sync(0xffffffffu, accb1, o);
        accb2 += __shfl_xor_sync(0xffffffffu, accb2, o);
        accb3 += __shfl_xor_sync(0xffffffffu, accb3, o);
    }
    if (lane == 0) {
        d_bias[(size_t)0 * MM + r] = accb0;
        d_bias[(size_t)1 * MM + r] = accb1;
        d_bias[(size_t)2 * MM + r] = accb2;
        d_bias[(size_t)3 * MM + r] = accb3;
    }
}

// ---------------------------------------------------------------------------
// Kernel 2: projections, persistent-W tf32 mma.sync GEMM.
// Grid = 148 slots x 2 halves. Block keeps 256 W cols resident (Wt[n][k],
// stride 132, conflict-free frags), loops over M-tiles with double-buffered
// X prefetch (regs->smem). Warp = m32 x 64 cols.
// ---------------------------------------------------------------------------
#define PJ_S 132
#define PJ_W_FLOATS (256 * PJ_S)          // 33792
#define PJ_X_FLOATS (64 * PJ_S)           // 8448 per buffer
#define PROJ_SMEM_FLOATS (PJ_W_FLOATS + 2 * PJ_X_FLOATS)   // 50688 -> 202752 B

__global__ __launch_bounds__(256) void proj_gemm_tc(
    const float* __restrict__ wq, const float* __restrict__ wk,
    const float* __restrict__ wv, const float* __restrict__ wg)
{
    extern __shared__ float ps[];
    float* Wt = ps;                        // [256][132]
    float* Xb = ps + PJ_W_FLOATS;          // [2][64][132]

    int tid = threadIdx.x, lane = tid & 31, warp = tid >> 5;
    int g = lane >> 2, t = lane & 3;
    int slot = blockIdx.x;                 // 0..147
    int half = blockIdx.y;                 // 0..1
    int mhalf = warp >> 2;                 // 0..1 -> rows mhalf*32..+31
    int cq = warp & 3;                     // 0..3 -> cols cq*64..+63

    // Stage W once: Wt[n][k], n = col within this 256-col half (tf32-rounded)
    const float* w0 = (half == 0) ? wq : wv;
    const float* w1 = (half == 0) ? wk : wg;
    for (int i = tid; i < 256 * 128; i += 256) {
        int n = i & 255, k = i >> 8;       // consecutive tid -> consecutive n (coalesced)
        const float* w = (n < 128) ? w0 : w1;
        Wt[n * PJ_S + k] = __uint_as_float(cvt_tf32(w[(size_t)k * 128 + (n & 127)]));
    }

    // Stage first tile into buffer 0 (row = j*8 + tid/32, col = (tid%32)*4)
    {
        int m0 = slot * 64;
        int rsub = tid >> 5, col = (tid & 31) * 4;
        #pragma unroll
        for (int j = 0; j < 8; j++) {
            int row = j * 8 + rsub;
            float4 v = *(const float4*)&d_x[(size_t)(m0 + row) * 128 + col];
            float4 o;
            o.x = __uint_as_float(cvt_tf32(v.x));
            o.y = __uint_as_float(cvt_tf32(v.y));
            o.z = __uint_as_float(cvt_tf32(v.z));
            o.w = __uint_as_float(cvt_tf32(v.w));
            *(float4*)&Xb[row * PJ_S + col] = o;
        }
    }
    __syncthreads();

    float scale = (half == 0 && cq < 2) ? 0.17677669529663687f : 1.0f;
    int colbase = cq * 64;
    int buf = 0;

    for (int mtile = slot; mtile < 2304; mtile += 148) {
        int mnext = mtile + 148;
        bool has_next = (mnext < 2304);

        // Prefetch next X tile into registers (hidden under compute)
        float4 pf[8];
        if (has_next) {
            int rsub = tid >> 5, col = (tid & 31) * 4;
            const float* src = d_x + (size_t)(mnext * 64) * 128;
            #pragma unroll
            for (int j = 0; j < 8; j++)
                pf[j] = *(const float4*)&src[(size_t)(j * 8 + rsub) * 128 + col];
        }

        // Compute: warp tile m32 x 64 cols, 16 k8-steps
        const float* Xs = Xb + buf * PJ_X_FLOATS;
        float c[16][4];
        #pragma unroll
        for (int i = 0; i < 16; i++)
            #pragma unroll
            for (int j = 0; j < 4; j++) c[i][j] = 0.f;

        #pragma unroll 4
        for (int k8 = 0; k8 < 16; k8++) {
            int k0 = k8 * 8;
            int r0 = mhalf * 32;
            unsigned a0 = __float_as_uint(Xs[(r0 + g) * PJ_S + k0 + t]);
            unsigned a1 = __float_as_uint(Xs[(r0 + 8 + g) * PJ_S + k0 + t]);
            unsigned a2 = __float_as_uint(Xs[(r0 + g) * PJ_S + k0 + t + 4]);
            unsigned a3 = __float_as_uint(Xs[(r0 + 8 + g) * PJ_S + k0 + t + 4]);
            unsigned a4 = __float_as_uint(Xs[(r0 + 16 + g) * PJ_S + k0 + t]);
            unsigned a5 = __float_as_uint(Xs[(r0 + 24 + g) * PJ_S + k0 + t]);
            unsigned a6 = __float_as_uint(Xs[(r0 + 16 + g) * PJ_S + k0 + t + 4]);
            unsigned a7 = __float_as_uint(Xs[(r0 + 24 + g) * PJ_S + k0 + t + 4]);
            #pragma unroll
            for (int nb = 0; nb < 8; nb++) {
                unsigned b0 = __float_as_uint(Wt[(colbase + nb * 8 + g) * PJ_S + k0 + t]);
                unsigned b1 = __float_as_uint(Wt[(colbase + nb * 8 + g) * PJ_S + k0 + t + 4]);
                mma_tf32(c[nb][0], c[nb][1], c[nb][2], c[nb][3],
                         a0, a1, a2, a3, b0, b1);
                mma_tf32(c[8 + nb][0], c[8 + nb][1], c[8 + nb][2], c[8 + nb][3],
                         a4, a5, a6, a7, b0, b1);
            }
        }

        // Store (q columns pre-scaled)
        {
            int m0 = mtile * 64;
            int r = m0 + mhalf * 32;
            #pragma unroll
            for (int nb = 0; nb < 8; nb++) {
                int col = half * 256 + colbase + nb * 8 + 2 * t;
                *(float2*)&d_y[(size_t)(r + g) * 512 + col] =
                    make_float2(c[nb][0] * scale, c[nb][1] * scale);
                *(float2*)&d_y[(size_t)(r + 8 + g) * 512 + col] =
                    make_float2(c[nb][2] * scale, c[nb][3] * scale);
                *(float2*)&d_y[(size_t)(r + 16 + g) * 512 + col] =
                    make_float2(c[8 + nb][0] * scale, c[8 + nb][1] * scale);
                *(float2*)&d_y[(size_t)(r + 24 + g) * 512 + col] =
                    make_float2(c[8 + nb][2] * scale, c[8 + nb][3] * scale);
            }
        }

        __syncthreads();
        if (has_next) {
            float* dst = Xb + (buf ^ 1) * PJ_X_FLOATS;
            int rsub = tid >> 5, col = (tid & 31) * 4;
            #pragma unroll
            for (int j = 0; j < 8; j++) {
                float4 v = pf[j];
                float4 o;
                o.x = __uint_as_float(cvt_tf32(v.x));
                o.y = __uint_as_float(cvt_tf32(v.y));
                o.z = __uint_as_float(cvt_tf32(v.z));
                o.w = __uint_as_float(cvt_tf32(v.w));
                *(float4*)&dst[(j * 8 + rsub) * PJ_S + col] = o;
            }
        }
        __syncthreads();
        buf ^= 1;
    }
}

// ---------------------------------------------------------------------------
// Kernel 3: attention per (b,h), register-resident flash (tf32 mma.sync).
// 256 threads = 8 warps; warp owns 3 m16 q-tiles. (Unchanged from R6.)
// ---------------------------------------------------------------------------
#define KT_STRIDE 392
#define VS_STRIDE 40
#define SM_KT   0
#define SM_VS   12544
#define SM_AM   27904
#define ATTN_SMEM_FLOATS 28288

__global__ __launch_bounds__(256) void attn_kernel(const int* __restrict__ mask)
{
    extern __shared__ float sm[];
    float* Kt = sm + SM_KT;
    float* Vs = sm + SM_VS;
    float* Am = sm + SM_AM;

    int b = blockIdx.x, h = blockIdx.y;
    int tid = threadIdx.x, lane = tid & 31, w = tid >> 5;
    int g = lane >> 2, t = lane & 3;
    const float* Yb = d_y + (size_t)b * (NN * 512);

    for (int idx = tid; idx < NN * 32; idx += 256) {
        int key = idx >> 5, d = idx & 31;
        Kt[d * KT_STRIDE + key] =
            __uint_as_float(cvt_tf32(Yb[(size_t)key * 512 + 128 + h * 32 + d]));
        Vs[key * VS_STRIDE + d] =
            __uint_as_float(cvt_tf32(Yb[(size_t)key * 512 + 256 + h * 32 + d]));
    }
    for (int k = tid; k < NN; k += 256)
        Am[k] = (mask[(size_t)b * NN + k] != 0) ? 0.f : -1e9f;
    __syncthreads();

    int src1 = (lane & ~3) | (t >> 1);
    int src2 = src1 + 2;
    bool odd = (t & 1);

    for (int mt = w; mt < 24; mt += 8) {
        int q0 = mt * 16;

        unsigned aq[4][4];
        #pragma unroll
        for (int s = 0; s < 4; s++) {
            const float* qp = Yb + (size_t)q0 * 512 + h * 32 + s * 8 + t;
            aq[s][0] = cvt_tf32(qp[(size_t)g * 512]);
            aq[s][1] = cvt_tf32(qp[(size_t)(g + 8) * 512]);
            aq[s][2] = cvt_tf32(qp[(size_t)g * 512 + 4]);
            aq[s][3] = cvt_tf32(qp[(size_t)(g + 8) * 512 + 4]);
        }

        float oc[4][4];
        #pragma unroll
        for (int dn = 0; dn < 4; dn++)
            #pragma unroll
            for (int j = 0; j < 4; j++) oc[dn][j] = 0.f;
        float sum_lo = 0.f, sum_hi = 0.f;

        const float* br_lo = d_bias + (size_t)h * MM + (size_t)(q0 + g) * NN;
        const float* br_hi = br_lo + (size_t)8 * NN;

        for (int kb = 0; kb < 6; kb++) {
            float pc[8][4];

            #pragma unroll
            for (int nb = 0; nb < 8; nb++) {
                int k8 = kb * 64 + nb * 8;
                float c0 = 0.f, c1 = 0.f, c2 = 0.f, c3 = 0.f;
                #pragma unroll
                for (int s = 0; s < 4; s++) {
                    unsigned b0 = __float_as_uint(Kt[(s * 8 + t) * KT_STRIDE + k8 + g]);
                    unsigned b1 = __float_as_uint(Kt[(s * 8 + t + 4) * KT_STRIDE + k8 + g]);
                    mma_tf32(c0, c1, c2, c3,
                             aq[s][0], aq[s][1], aq[s][2], aq[s][3], b0, b1);
                }
                int col = k8 + 2 * t;
                float2 blo = *(const float2*)&br_lo[col];
                float2 bhi = *(const float2*)&br_hi[col];
                float2 am  = *(const float2*)&Am[col];
                float e0 = __expf(c0 + blo.x + am.x);
                float e1 = __expf(c1 + blo.y + am.y);
                float e2 = __expf(c2 + bhi.x + am.x);
                float e3 = __expf(c3 + bhi.y + am.y);
                sum_lo += e0 + e1;
                sum_hi += e2 + e3;
                pc[nb][0] = e0; pc[nb][1] = e1; pc[nb][2] = e2; pc[nb][3] = e3;
            }

            #pragma unroll
            for (int j = 0; j < 8; j++) {
                float x0 = __shfl_sync(0xffffffffu, pc[j][0], src1);
                float x1 = __shfl_sync(0xffffffffu, pc[j][1], src1);
                float x2 = __shfl_sync(0xffffffffu, pc[j][2], src1);
                float x3 = __shfl_sync(0xffffffffu, pc[j][3], src1);
                float y0 = __shfl_sync(0xffffffffu, pc[j][0], src2);
                float y1 = __shfl_sync(0xffffffffu, pc[j][1], src2);
                float y2 = __shfl_sync(0xffffffffu, pc[j][2], src2);
                float y3 = __shfl_sync(0xffffffffu, pc[j][3], src2);
                unsigned a0 = cvt_tf32(odd ? x1 : x0);
                unsigned a1 = cvt_tf32(odd ? x3 : x2);
                unsigned a2 = cvt_tf32(odd ? y1 : y0);
                unsigned a3 = cvt_tf32(odd ? y3 : y2);
                int kg = kb * 64 + j * 8;
                #pragma unroll
                for (int dn = 0; dn < 4; dn++) {
                    unsigned b0 = __float_as_uint(Vs[(kg + t) * VS_STRIDE + dn * 8 + g]);
                    unsigned b1 = __float_as_uint(Vs[(kg + t + 4) * VS_STRIDE + dn * 8 + g]);
                    mma_tf32(oc[dn][0], oc[dn][1], oc[dn][2], oc[dn][3],
                             a0, a1, a2, a3, b0, b1);
                }
            }
        }

        #pragma unroll
        for (int o = 1; o <= 2; o <<= 1) {
            sum_lo += __shfl_xor_sync(0xffffffffu, sum_lo, o);
            sum_hi += __shfl_xor_sync(0xffffffffu, sum_hi, o);
        }
        float inv_lo = 1.f / sum_lo;
        float inv_hi = 1.f / sum_hi;

        float* ob = d_o + ((size_t)b * NN + q0) * CC + h * 32;
        #pragma unroll
        for (int dn = 0; dn < 4; dn++) {
            *(float2*)&ob[(size_t)g * CC + dn * 8 + 2 * t] =
                make_float2(oc[dn][0] * inv_lo, oc[dn][1] * inv_lo);
            *(float2*)&ob[(size_t)(g + 8) * CC + dn * 8 + 2 * t] =
                make_float2(oc[dn][2] * inv_hi, oc[dn][3] * inv_hi);
        }
    }
}

// ---------------------------------------------------------------------------
// Kernel 4: out = (o * sigmoid(g)) @ wo. Scalar FFMA (unchanged from R6).
// ---------------------------------------------------------------------------
__global__ __launch_bounds__(256) void out_gemm(
    const float* __restrict__ wo, float* __restrict__ out)
{
    __shared__ float As[64][64];
    __shared__ float Bs[64][64];

    int m0 = blockIdx.x * 64;
    int n0 = blockIdx.y * 64;
    int tx = threadIdx.x & 15, ty = threadIdx.x >> 4;
    float acc[4][4] = {};

    for (int kk = 0; kk < 128; kk += 64) {
        #pragma unroll
        for (int i = 0; i < 4; i++) {
            int idx = threadIdx.x + i * 256;
            int row = idx >> 4, c4 = (idx & 15) * 4;
            float4 ov = *(const float4*)&d_o[(size_t)(m0 + row) * 128 + kk + c4];
            float4 gv = *(const float4*)&d_y[(size_t)(m0 + row) * 512 + 384 + kk + c4];
            float4 a;
            a.x = ov.x * (1.f / (1.f + __expf(-gv.x)));
            a.y = ov.y * (1.f / (1.f + __expf(-gv.y)));
            a.z = ov.z * (1.f / (1.f + __expf(-gv.z)));
            a.w = ov.w * (1.f / (1.f + __expf(-gv.w)));
            *(float4*)&As[row][c4] = a;
            *(float4*)&Bs[row][c4] =
                *(const float4*)&wo[(size_t)(kk + row) * 128 + n0 + c4];
        }
        __syncthreads();
        #pragma unroll 8
        for (int k = 0; k < 64; k++) {
            float4 b4 = *(float4*)&Bs[k][tx * 4];
            float a0 = As[ty*4+0][k], a1 = As[ty*4+1][k];
            float a2 = As[ty*4+2][k], a3 = As[ty*4+3][k];
            acc[0][0] += a0*b4.x; acc[0][1] += a0*b4.y; acc[0][2] += a0*b4.z; acc[0][3] += a0*b4.w;
            acc[1][0] += a1*b4.x; acc[1][1] += a1*b4.y; acc[1][2] += a1*b4.z; acc[1][3] += a1*b4.w;
            acc[2][0] += a2*b4.x; acc[2][1] += a2*b4.y; acc[2][2] += a2*b4.z; acc[2][3] += a2*b4.w;
            acc[3][0] += a3*b4.x; acc[3][1] += a3*b4.y; acc[3][2] += a3*b4.z; acc[3][3] += a3*b4.w;
        }
        __syncthreads();
    }

    #pragma unroll
    for (int i = 0; i < 4; i++) {
        float4 r;
        r.x = acc[i][0]; r.y = acc[i][1]; r.z = acc[i][2]; r.w = acc[i][3];
        *(float4*)&out[(size_t)(m0 + ty*4 + i) * 128 + n0 + tx*4] = r;
    }
}

// ---------------------------------------------------------------------------
extern "C" void kernel_launch(void* const* d_in, const int* in_sizes, int n_in,
                              void* d_out, int out_size)
{
    const float* pair   = (const float*)d_in[0];
    const int*   mask   = (const int*)d_in[1];
    const float* ln_w   = (const float*)d_in[2];
    const float* ln_b   = (const float*)d_in[3];
    const float* w_bias = (const float*)d_in[4];
    const float* wq     = (const float*)d_in[5];
    const float* wk     = (const float*)d_in[6];
    const float* wv     = (const float*)d_in[7];
    const float* wg     = (const float*)d_in[8];
    const float* wo     = (const float*)d_in[9];
    float* out = (float*)d_out;

    (void)in_sizes; (void)n_in; (void)out_size;

    ln_bias_kernel<<<MM / 8, 256>>>(pair, ln_w, ln_b, w_bias);

    size_t proj_smem = (size_t)PROJ_SMEM_FLOATS * sizeof(float);
    cudaFuncSetAttribute(proj_gemm_tc,
                         cudaFuncAttributeMaxDynamicSharedMemorySize,
                         (int)proj_smem);
    proj_gemm_tc<<<dim3(148, 2), 256, proj_smem>>>(wq, wk, wv, wg);

    size_t attn_smem = (size_t)ATTN_SMEM_FLOATS * sizeof(float);
    cudaFuncSetAttribute(attn_kernel,
                         cudaFuncAttributeMaxDynamicSharedMemorySize,
                         (int)attn_smem);
    attn_kernel<<<dim3(NN, HH), 256, attn_smem>>>(mask);

    out_gemm<<<dim3(MM / 64, 2), 256>>>(wo, out);
}

// round 12
// speedup vs baseline: 2.3980x; 1.5232x over previous
#include <cuda_runtime.h>
#include <cuda_fp16.h>
#include <math.h>
#include <stdint.h>

#define NN 384
#define CC 128
#define HH 4
#define MM (NN*NN)

// Scratch (allocation-free: __device__ globals)
__device__ float  d_x[(size_t)MM*CC];      // layernormed pair (fp32)
__device__ __half d_y[(size_t)MM*512];     // [q|k|v|g] as fp16, q pre-scaled
__device__ float  d_bias[(size_t)HH*MM];   // bias[h, q, k] (fp32)
__device__ float  d_o[(size_t)MM*CC];      // attention output (fp32)

// ---- fp16 tensor-core helpers (m16n8k16, fp32 accum) ----
__device__ __forceinline__ void mma_f16(float& c0, float& c1, float& c2, float& c3,
                                        unsigned a0, unsigned a1, unsigned a2, unsigned a3,
                                        unsigned b0, unsigned b1) {
    asm("mma.sync.aligned.m16n8k16.row.col.f32.f16.f16.f32 "
        "{%0,%1,%2,%3}, {%4,%5,%6,%7}, {%8,%9}, {%0,%1,%2,%3};"
        : "+f"(c0), "+f"(c1), "+f"(c2), "+f"(c3)
        : "r"(a0), "r"(a1), "r"(a2), "r"(a3), "r"(b0), "r"(b1));
}
__device__ __forceinline__ unsigned h2u(float lo, float hi) {
    __half2 h = __floats2half2_rn(lo, hi);
    return reinterpret_cast<unsigned&>(h);
}

// ---------------------------------------------------------------------------
// Kernel 1: LayerNorm + pair bias (unchanged).
// ---------------------------------------------------------------------------
__global__ __launch_bounds__(256) void ln_bias_kernel(
    const float* __restrict__ pair,
    const float* __restrict__ ln_w,
    const float* __restrict__ ln_b,
    const float* __restrict__ w_bias)
{
    int warp = threadIdx.x >> 5, lane = threadIdx.x & 31;
    int r = blockIdx.x * 8 + warp;
    if (r >= MM) return;

    float4 v = ((const float4*)(pair + (size_t)r * CC))[lane];
    float s  = v.x + v.y + v.z + v.w;
    float sq = v.x*v.x + v.y*v.y + v.z*v.z + v.w*v.w;
    #pragma unroll
    for (int o = 16; o; o >>= 1) {
        s  += __shfl_xor_sync(0xffffffffu, s,  o);
        sq += __shfl_xor_sync(0xffffffffu, sq, o);
    }
    float mean = s * (1.0f / CC);
    float var  = sq * (1.0f / CC) - mean * mean;
    float inv  = rsqrtf(var + 1e-5f);

    float4 w = ((const float4*)ln_w)[lane];
    float4 b = ((const float4*)ln_b)[lane];
    float4 xn;
    xn.x = (v.x - mean) * inv * w.x + b.x;
    xn.y = (v.y - mean) * inv * w.y + b.y;
    xn.z = (v.z - mean) * inv * w.z + b.z;
    xn.w = (v.w - mean) * inv * w.w + b.w;
    ((float4*)(d_x + (size_t)r * CC))[lane] = xn;

    float accb0 = 0.f, accb1 = 0.f, accb2 = 0.f, accb3 = 0.f;
    float xv[4] = {xn.x, xn.y, xn.z, xn.w};
    #pragma unroll
    for (int i = 0; i < 4; i++) {
        float4 wb = ((const float4*)w_bias)[lane * 4 + i];
        accb0 += xv[i] * wb.x;
        accb1 += xv[i] * wb.y;
        accb2 += xv[i] * wb.z;
        accb3 += xv[i] * wb.w;
    }
    #pragma unroll
    for (int o = 16; o; o >>= 1) {
        accb0 += __shfl_xor_sync(0xffffffffu, accb0, o);
        accb1 += __shfl_xor_sync(0xffffffffu, accb1, o);
        accb2 += __shfl_xor_sync(0xffffffffu, accb2, o);
        accb3 += __shfl_xor_sync(0xffffffffu, accb3, o);
    }
    if (lane == 0) {
        d_bias[(size_t)0 * MM + r] = accb0;
        d_bias[(size_t)1 * MM + r] = accb1;
        d_bias[(size_t)2 * MM + r] = accb2;
        d_bias[(size_t)3 * MM + r] = accb3;
    }
}

// ---------------------------------------------------------------------------
// Kernel 2: projections, persistent-W fp16 m16n8k16 GEMM. Y stored as fp16.
// Grid (148,2). Block keeps 256 W cols resident as half Wt[n][k] (stride 136:
// frag bank 4g+t conflict-free). Double-buffered X prefetch. Warp = m32 x 64.
// ---------------------------------------------------------------------------
#define PJW 136
#define PROJ_SMEM_BYTES ((256*PJW + 2*64*PJW) * 2)   // 104448

__global__ __launch_bounds__(256) void proj_fp16(
    const float* __restrict__ wq, const float* __restrict__ wk,
    const float* __restrict__ wv, const float* __restrict__ wg)
{
    extern __shared__ char psm[];
    __half* Wt = (__half*)psm;                 // [256][136]
    __half* Xb = Wt + 256 * PJW;               // [2][64][136]

    int tid = threadIdx.x, lane = tid & 31, warp = tid >> 5;
    int g = lane >> 2, t = lane & 3;
    int slot = blockIdx.x;
    int ph = blockIdx.y;                       // 0: wq|wk, 1: wv|wg
    int mhalf = warp >> 2;
    int cq = warp & 3;

    const float* w0 = (ph == 0) ? wq : wv;
    const float* w1 = (ph == 0) ? wk : wg;
    for (int i = tid; i < 256 * 128; i += 256) {
        int n = i & 255, k = i >> 8;
        const float* w = (n < 128) ? w0 : w1;
        Wt[n * PJW + k] = __float2half(w[(size_t)k * 128 + (n & 127)]);
    }

    {
        int m0 = slot * 64;
        int rsub = tid >> 5, col = (tid & 31) * 4;
        #pragma unroll
        for (int j = 0; j < 8; j++) {
            int row = j * 8 + rsub;
            float4 v = *(const float4*)&d_x[(size_t)(m0 + row) * 128 + col];
            uint2 o;
            o.x = h2u(v.x, v.y);
            o.y = h2u(v.z, v.w);
            *(uint2*)&Xb[row * PJW + col] = o;
        }
    }
    __syncthreads();

    float scale = (ph == 0 && cq < 2) ? 0.17677669529663687f : 1.0f;
    int colbase = cq * 64;
    int buf = 0;

    for (int mtile = slot; mtile < 2304; mtile += 148) {
        int mnext = mtile + 148;
        bool has_next = (mnext < 2304);

        float4 pf[8];
        if (has_next) {
            int rsub = tid >> 5, col = (tid & 31) * 4;
            const float* src = d_x + (size_t)(mnext * 64) * 128;
            #pragma unroll
            for (int j = 0; j < 8; j++)
                pf[j] = *(const float4*)&src[(size_t)(j * 8 + rsub) * 128 + col];
        }

        const __half* Xs = Xb + buf * (64 * PJW);
        float c[16][4];
        #pragma unroll
        for (int i = 0; i < 16; i++)
            #pragma unroll
            for (int j = 0; j < 4; j++) c[i][j] = 0.f;

        int r0 = mhalf * 32;
        #pragma unroll
        for (int k16 = 0; k16 < 8; k16++) {
            int k0 = k16 * 16;
            unsigned a0 = *(const unsigned*)&Xs[(r0 + g) * PJW + k0 + 2*t];
            unsigned a1 = *(const unsigned*)&Xs[(r0 + 8 + g) * PJW + k0 + 2*t];
            unsigned a2 = *(const unsigned*)&Xs[(r0 + g) * PJW + k0 + 2*t + 8];
            unsigned a3 = *(const unsigned*)&Xs[(r0 + 8 + g) * PJW + k0 + 2*t + 8];
            unsigned a4 = *(const unsigned*)&Xs[(r0 + 16 + g) * PJW + k0 + 2*t];
            unsigned a5 = *(const unsigned*)&Xs[(r0 + 24 + g) * PJW + k0 + 2*t];
            unsigned a6 = *(const unsigned*)&Xs[(r0 + 16 + g) * PJW + k0 + 2*t + 8];
            unsigned a7 = *(const unsigned*)&Xs[(r0 + 24 + g) * PJW + k0 + 2*t + 8];
            #pragma unroll
            for (int nb = 0; nb < 8; nb++) {
                int n = colbase + nb * 8 + g;
                unsigned b0 = *(const unsigned*)&Wt[n * PJW + k0 + 2*t];
                unsigned b1 = *(const unsigned*)&Wt[n * PJW + k0 + 2*t + 8];
                mma_f16(c[nb][0], c[nb][1], c[nb][2], c[nb][3],
                        a0, a1, a2, a3, b0, b1);
                mma_f16(c[8+nb][0], c[8+nb][1], c[8+nb][2], c[8+nb][3],
                        a4, a5, a6, a7, b0, b1);
            }
        }

        {
            int r = mtile * 64 + mhalf * 32;
            #pragma unroll
            for (int nb = 0; nb < 8; nb++) {
                int col = ph * 256 + colbase + nb * 8 + 2 * t;
                *(unsigned*)&d_y[(size_t)(r + g) * 512 + col] =
                    h2u(c[nb][0] * scale, c[nb][1] * scale);
                *(unsigned*)&d_y[(size_t)(r + 8 + g) * 512 + col] =
                    h2u(c[nb][2] * scale, c[nb][3] * scale);
                *(unsigned*)&d_y[(size_t)(r + 16 + g) * 512 + col] =
                    h2u(c[8+nb][0] * scale, c[8+nb][1] * scale);
                *(unsigned*)&d_y[(size_t)(r + 24 + g) * 512 + col] =
                    h2u(c[8+nb][2] * scale, c[8+nb][3] * scale);
            }
        }

        __syncthreads();
        if (has_next) {
            __half* dst = Xb + (buf ^ 1) * (64 * PJW);
            int rsub = tid >> 5, col = (tid & 31) * 4;
            #pragma unroll
            for (int j = 0; j < 8; j++) {
                float4 v = pf[j];
                uint2 o;
                o.x = h2u(v.x, v.y);
                o.y = h2u(v.z, v.w);
                *(uint2*)&dst[(j * 8 + rsub) * PJW + col] = o;
            }
        }
        __syncthreads();
        buf ^= 1;
    }
}

// ---------------------------------------------------------------------------
// Kernel 3: attention per (b,h), fp16 m16n8k16 flash. No shuffles in P->A.
// Ks[key][40]h (QK^T B-frags, bank 20g+t distinct), Vt[d][392]h (PV B-frags,
// bank 4g+t). Softmax fp32, no max-subtraction (small logits). d_o fp32.
// ---------------------------------------------------------------------------
#define AKS 40
#define AVS 392
#define ATTN_SMEM_BYTES (384*AKS*2 + 32*AVS*2 + 384*4)   // 30720+25088+1536

__global__ __launch_bounds__(256) void attn_fp16(const int* __restrict__ mask)
{
    extern __shared__ char asm_[];
    __half* Ks = (__half*)asm_;                     // [384][40]
    __half* Vt = Ks + 384 * AKS;                    // [32][392]
    float*  Am = (float*)(Vt + 32 * AVS);           // [384]

    int b = blockIdx.x, h = blockIdx.y;
    int tid = threadIdx.x, lane = tid & 31, w = tid >> 5;
    int g = lane >> 2, t = lane & 3;
    const __half* Yb = d_y + (size_t)b * (NN * 512);

    // K: copy half4 chunks (already fp16)
    for (int idx = tid; idx < 384 * 8; idx += 256) {
        int key = idx >> 3, d4 = (idx & 7) * 4;
        uint2 v = *(const uint2*)&Yb[(size_t)key * 512 + 128 + h * 32 + d4];
        *(uint2*)&Ks[key * AKS + d4] = v;
    }
    // V transposed: Vt[d][key]
    for (int idx = tid; idx < 384 * 32; idx += 256) {
        int key = idx >> 5, d = idx & 31;
        Vt[d * AVS + key] = Yb[(size_t)key * 512 + 256 + h * 32 + d];
    }
    for (int k = tid; k < NN; k += 256)
        Am[k] = (mask[(size_t)b * NN + k] != 0) ? 0.f : -1e9f;
    __syncthreads();

    for (int mt = w; mt < 24; mt += 8) {
        int q0 = mt * 16;

        // Q A-fragments (half2 pairs straight from d_y; q pre-scaled)
        unsigned aq[2][4];
        #pragma unroll
        for (int s = 0; s < 2; s++) {
            int dc = h * 32 + 16 * s + 2 * t;
            aq[s][0] = *(const unsigned*)&Yb[(size_t)(q0 + g) * 512 + dc];
            aq[s][1] = *(const unsigned*)&Yb[(size_t)(q0 + 8 + g) * 512 + dc];
            aq[s][2] = *(const unsigned*)&Yb[(size_t)(q0 + g) * 512 + dc + 8];
            aq[s][3] = *(const unsigned*)&Yb[(size_t)(q0 + 8 + g) * 512 + dc + 8];
        }

        float oc[4][4];
        #pragma unroll
        for (int dn = 0; dn < 4; dn++)
            #pragma unroll
            for (int j = 0; j < 4; j++) oc[dn][j] = 0.f;
        float sum_lo = 0.f, sum_hi = 0.f;

        const float* br_lo = d_bias + (size_t)h * MM + (size_t)(q0 + g) * NN;
        const float* br_hi = br_lo + (size_t)8 * NN;

        for (int kb = 0; kb < 6; kb++) {
            float pc[8][4];

            // QK^T + bias + mask + exp
            #pragma unroll
            for (int nb = 0; nb < 8; nb++) {
                int k8 = kb * 64 + nb * 8;
                float c0 = 0.f, c1 = 0.f, c2 = 0.f, c3 = 0.f;
                #pragma unroll
                for (int s = 0; s < 2; s++) {
                    unsigned b0 = *(const unsigned*)&Ks[(k8 + g) * AKS + 16*s + 2*t];
                    unsigned b1 = *(const unsigned*)&Ks[(k8 + g) * AKS + 16*s + 2*t + 8];
                    mma_f16(c0, c1, c2, c3,
                            aq[s][0], aq[s][1], aq[s][2], aq[s][3], b0, b1);
                }
                int col = k8 + 2 * t;
                float2 blo = *(const float2*)&br_lo[col];
                float2 bhi = *(const float2*)&br_hi[col];
                float2 am  = *(const float2*)&Am[col];
                float e0 = __expf(c0 + blo.x + am.x);
                float e1 = __expf(c1 + blo.y + am.y);
                float e2 = __expf(c2 + bhi.x + am.x);
                float e3 = __expf(c3 + bhi.y + am.y);
                sum_lo += e0 + e1;
                sum_hi += e2 + e3;
                pc[nb][0] = e0; pc[nb][1] = e1; pc[nb][2] = e2; pc[nb][3] = e3;
            }

            // PV: P C-frags pack DIRECTLY into fp16 A-frags (no shuffles)
            #pragma unroll
            for (int j = 0; j < 4; j++) {
                unsigned a0 = h2u(pc[2*j][0],   pc[2*j][1]);
                unsigned a1 = h2u(pc[2*j][2],   pc[2*j][3]);
                unsigned a2 = h2u(pc[2*j+1][0], pc[2*j+1][1]);
                unsigned a3 = h2u(pc[2*j+1][2], pc[2*j+1][3]);
                int kg = kb * 64 + j * 16;
                #pragma unroll
                for (int dn = 0; dn < 4; dn++) {
                    unsigned b0 = *(const unsigned*)&Vt[(dn*8 + g) * AVS + kg + 2*t];
                    unsigned b1 = *(const unsigned*)&Vt[(dn*8 + g) * AVS + kg + 2*t + 8];
                    mma_f16(oc[dn][0], oc[dn][1], oc[dn][2], oc[dn][3],
                            a0, a1, a2, a3, b0, b1);
                }
            }
        }

        #pragma unroll
        for (int o = 1; o <= 2; o <<= 1) {
            sum_lo += __shfl_xor_sync(0xffffffffu, sum_lo, o);
            sum_hi += __shfl_xor_sync(0xffffffffu, sum_hi, o);
        }
        float inv_lo = 1.f / sum_lo;
        float inv_hi = 1.f / sum_hi;

        float* ob = d_o + ((size_t)b * NN + q0) * CC + h * 32;
        #pragma unroll
        for (int dn = 0; dn < 4; dn++) {
            *(float2*)&ob[(size_t)g * CC + dn * 8 + 2 * t] =
                make_float2(oc[dn][0] * inv_lo, oc[dn][1] * inv_lo);
            *(float2*)&ob[(size_t)(g + 8) * CC + dn * 8 + 2 * t] =
                make_float2(oc[dn][2] * inv_hi, oc[dn][3] * inv_hi);
        }
    }
}

// ---------------------------------------------------------------------------
// Kernel 4: out = (o * sigmoid(g)) @ wo, persistent-W fp16 m16n8k16.
// Grid 592 (4 CTA/SM). Gate from fp16 d_y fused into A staging.
// ---------------------------------------------------------------------------
#define OGW 136
#define OUT_SMEM_BYTES ((128*OGW + 64*OGW) * 2)   // 52224

__global__ __launch_bounds__(256) void out_fp16(
    const float* __restrict__ wo, float* __restrict__ out)
{
    extern __shared__ char osm[];
    __half* Wh = (__half*)osm;            // [128][136]  Wh[n][k] = wo[k][n]
    __half* Ah = Wh + 128 * OGW;          // [64][136]

    int tid = threadIdx.x, lane = tid & 31, warp = tid >> 5;
    int g = lane >> 2, t = lane & 3;
    int mhalf = warp >> 2;
    int cq = warp & 3;

    for (int i = tid; i < 128 * 128; i += 256) {
        int n = i & 127, k = i >> 7;
        Wh[n * OGW + k] = __float2half(wo[(size_t)k * 128 + n]);
    }

    for (int tile = blockIdx.x; tile < 2304; tile += 592) {
        int m0 = tile * 64;
        __syncthreads();   // W staged (first iter) / previous compute done
        for (int i = tid; i < 64 * 32; i += 256) {
            int row = i >> 5, c4 = (i & 31) * 4;
            float4 ov = *(const float4*)&d_o[(size_t)(m0 + row) * 128 + c4];
            uint2 gu = *(const uint2*)&d_y[(size_t)(m0 + row) * 512 + 384 + c4];
            __half2 g01 = reinterpret_cast<__half2&>(gu.x);
            __half2 g23 = reinterpret_cast<__half2&>(gu.y);
            float2 gf01 = __half22float2(g01);
            float2 gf23 = __half22float2(g23);
            float a0 = ov.x * (1.f / (1.f + __expf(-gf01.x)));
            float a1 = ov.y * (1.f / (1.f + __expf(-gf01.y)));
            float a2 = ov.z * (1.f / (1.f + __expf(-gf23.x)));
            float a3 = ov.w * (1.f / (1.f + __expf(-gf23.y)));
            uint2 o;
            o.x = h2u(a0, a1);
            o.y = h2u(a2, a3);
            *(uint2*)&Ah[row * OGW + c4] = o;
        }
        __syncthreads();

        float c[2][4][4];
        #pragma unroll
        for (int mm = 0; mm < 2; mm++)
            #pragma unroll
            for (int nb = 0; nb < 4; nb++)
                #pragma unroll
                for (int j = 0; j < 4; j++) c[mm][nb][j] = 0.f;

        #pragma unroll
        for (int k16 = 0; k16 < 8; k16++) {
            int k0 = k16 * 16;
            #pragma unroll
            for (int mm = 0; mm < 2; mm++) {
                int r0 = mhalf * 32 + mm * 16;
                unsigned a0 = *(const unsigned*)&Ah[(r0 + g) * OGW + k0 + 2*t];
                unsigned a1 = *(const unsigned*)&Ah[(r0 + 8 + g) * OGW + k0 + 2*t];
                unsigned a2 = *(const unsigned*)&Ah[(r0 + g) * OGW + k0 + 2*t + 8];
                unsigned a3 = *(const unsigned*)&Ah[(r0 + 8 + g) * OGW + k0 + 2*t + 8];
                #pragma unroll
                for (int nb = 0; nb < 4; nb++) {
                    int n = cq * 32 + nb * 8 + g;
                    unsigned b0 = *(const unsigned*)&Wh[n * OGW + k0 + 2*t];
                    unsigned b1 = *(const unsigned*)&Wh[n * OGW + k0 + 2*t + 8];
                    mma_f16(c[mm][nb][0], c[mm][nb][1], c[mm][nb][2], c[mm][nb][3],
                            a0, a1, a2, a3, b0, b1);
                }
            }
        }

        #pragma unroll
        for (int mm = 0; mm < 2; mm++) {
            int r = m0 + mhalf * 32 + mm * 16;
            #pragma unroll
            for (int nb = 0; nb < 4; nb++) {
                int col = cq * 32 + nb * 8 + 2 * t;
                *(float2*)&out[(size_t)(r + g) * 128 + col] =
                    make_float2(c[mm][nb][0], c[mm][nb][1]);
                *(float2*)&out[(size_t)(r + 8 + g) * 128 + col] =
                    make_float2(c[mm][nb][2], c[mm][nb][3]);
            }
        }
    }
}

// ---------------------------------------------------------------------------
extern "C" void kernel_launch(void* const* d_in, const int* in_sizes, int n_in,
                              void* d_out, int out_size)
{
    const float* pair   = (const float*)d_in[0];
    const int*   mask   = (const int*)d_in[1];
    const float* ln_w   = (const float*)d_in[2];
    const float* ln_b   = (const float*)d_in[3];
    const float* w_bias = (const float*)d_in[4];
    const float* wq     = (const float*)d_in[5];
    const float* wk     = (const float*)d_in[6];
    const float* wv     = (const float*)d_in[7];
    const float* wg     = (const float*)d_in[8];
    const float* wo     = (const float*)d_in[9];
    float* out = (float*)d_out;

    (void)in_sizes; (void)n_in; (void)out_size;

    ln_bias_kernel<<<MM / 8, 256>>>(pair, ln_w, ln_b, w_bias);

    cudaFuncSetAttribute(proj_fp16,
                         cudaFuncAttributeMaxDynamicSharedMemorySize, PROJ_SMEM_BYTES);
    proj_fp16<<<dim3(148, 2), 256, PROJ_SMEM_BYTES>>>(wq, wk, wv, wg);

    cudaFuncSetAttribute(attn_fp16,
                         cudaFuncAttributeMaxDynamicSharedMemorySize, ATTN_SMEM_BYTES);
    attn_fp16<<<dim3(NN, HH), 256, ATTN_SMEM_BYTES>>>(mask);

    cudaFuncSetAttribute(out_fp16,
                         cudaFuncAttributeMaxDynamicSharedMemorySize, OUT_SMEM_BYTES);
    out_fp16<<<592, 256, OUT_SMEM_BYTES>>>(wo, out);
}

// round 13
// speedup vs baseline: 2.5378x; 1.0583x over previous
#include <cuda_runtime.h>
#include <cuda_fp16.h>
#include <math.h>
#include <stdint.h>

#define NN 384
#define CC 128
#define HH 4
#define MM (NN*NN)

// Scratch (allocation-free: __device__ globals)
__device__ __half d_x[(size_t)MM*CC];      // layernormed pair (fp16; bias computed fp32 before rounding)
__device__ __half d_y[(size_t)MM*512];     // [q|k|v|g] as fp16, q pre-scaled
__device__ float  d_bias[(size_t)HH*MM];   // bias[h, q, k] (fp32)
__device__ __half d_o[(size_t)MM*CC];      // attention output (fp16)

// ---- fp16 tensor-core helpers (m16n8k16, fp32 accum) ----
__device__ __forceinline__ void mma_f16(float& c0, float& c1, float& c2, float& c3,
                                        unsigned a0, unsigned a1, unsigned a2, unsigned a3,
                                        unsigned b0, unsigned b1) {
    asm("mma.sync.aligned.m16n8k16.row.col.f32.f16.f16.f32 "
        "{%0,%1,%2,%3}, {%4,%5,%6,%7}, {%8,%9}, {%0,%1,%2,%3};"
        : "+f"(c0), "+f"(c1), "+f"(c2), "+f"(c3)
        : "r"(a0), "r"(a1), "r"(a2), "r"(a3), "r"(b0), "r"(b1));
}
__device__ __forceinline__ unsigned h2u(float lo, float hi) {
    __half2 h = __floats2half2_rn(lo, hi);
    return reinterpret_cast<unsigned&>(h);
}

// ---------------------------------------------------------------------------
// Kernel 1: LayerNorm + pair bias. LN math fp32; x stored fp16.
// ---------------------------------------------------------------------------
__global__ __launch_bounds__(256) void ln_bias_kernel(
    const float* __restrict__ pair,
    const float* __restrict__ ln_w,
    const float* __restrict__ ln_b,
    const float* __restrict__ w_bias)
{
    int warp = threadIdx.x >> 5, lane = threadIdx.x & 31;
    int r = blockIdx.x * 8 + warp;
    if (r >= MM) return;

    float4 v = ((const float4*)(pair + (size_t)r * CC))[lane];
    float s  = v.x + v.y + v.z + v.w;
    float sq = v.x*v.x + v.y*v.y + v.z*v.z + v.w*v.w;
    #pragma unroll
    for (int o = 16; o; o >>= 1) {
        s  += __shfl_xor_sync(0xffffffffu, s,  o);
        sq += __shfl_xor_sync(0xffffffffu, sq, o);
    }
    float mean = s * (1.0f / CC);
    float var  = sq * (1.0f / CC) - mean * mean;
    float inv  = rsqrtf(var + 1e-5f);

    float4 w = ((const float4*)ln_w)[lane];
    float4 b = ((const float4*)ln_b)[lane];
    float4 xn;
    xn.x = (v.x - mean) * inv * w.x + b.x;
    xn.y = (v.y - mean) * inv * w.y + b.y;
    xn.z = (v.z - mean) * inv * w.z + b.z;
    xn.w = (v.w - mean) * inv * w.w + b.w;
    uint2 xo;
    xo.x = h2u(xn.x, xn.y);
    xo.y = h2u(xn.z, xn.w);
    *(uint2*)&d_x[(size_t)r * CC + lane * 4] = xo;

    float accb0 = 0.f, accb1 = 0.f, accb2 = 0.f, accb3 = 0.f;
    float xv[4] = {xn.x, xn.y, xn.z, xn.w};
    #pragma unroll
    for (int i = 0; i < 4; i++) {
        float4 wb = ((const float4*)w_bias)[lane * 4 + i];
        accb0 += xv[i] * wb.x;
        accb1 += xv[i] * wb.y;
        accb2 += xv[i] * wb.z;
        accb3 += xv[i] * wb.w;
    }
    #pragma unroll
    for (int o = 16; o; o >>= 1) {
        accb0 += __shfl_xor_sync(0xffffffffu, accb0, o);
        accb1 += __shfl_xor_sync(0xffffffffu, accb1, o);
        accb2 += __shfl_xor_sync(0xffffffffu, accb2, o);
        accb3 += __shfl_xor_sync(0xffffffffu, accb3, o);
    }
    if (lane == 0) {
        d_bias[(size_t)0 * MM + r] = accb0;
        d_bias[(size_t)1 * MM + r] = accb1;
        d_bias[(size_t)2 * MM + r] = accb2;
        d_bias[(size_t)3 * MM + r] = accb3;
    }
}

// ---------------------------------------------------------------------------
// Kernel 2: projections, persistent-W fp16 m16n8k16 GEMM. X already fp16.
// ---------------------------------------------------------------------------
#define PJW 136
#define PROJ_SMEM_BYTES ((256*PJW + 2*64*PJW) * 2)   // 104448

__global__ __launch_bounds__(256) void proj_fp16(
    const float* __restrict__ wq, const float* __restrict__ wk,
    const float* __restrict__ wv, const float* __restrict__ wg)
{
    extern __shared__ char psm[];
    __half* Wt = (__half*)psm;                 // [256][136]
    __half* Xb = Wt + 256 * PJW;               // [2][64][136]

    int tid = threadIdx.x, lane = tid & 31, warp = tid >> 5;
    int g = lane >> 2, t = lane & 3;
    int slot = blockIdx.x;
    int ph = blockIdx.y;                       // 0: wq|wk, 1: wv|wg
    int mhalf = warp >> 2;
    int cq = warp & 3;

    const float* w0 = (ph == 0) ? wq : wv;
    const float* w1 = (ph == 0) ? wk : wg;
    for (int i = tid; i < 256 * 128; i += 256) {
        int n = i & 255, k = i >> 8;
        const float* w = (n < 128) ? w0 : w1;
        Wt[n * PJW + k] = __float2half(w[(size_t)k * 128 + (n & 127)]);
    }

    {
        int m0 = slot * 64;
        int rsub = tid >> 5, col = (tid & 31) * 4;
        #pragma unroll
        for (int j = 0; j < 8; j++) {
            int row = j * 8 + rsub;
            uint2 v = *(const uint2*)&d_x[(size_t)(m0 + row) * 128 + col];
            *(uint2*)&Xb[row * PJW + col] = v;
        }
    }
    __syncthreads();

    float scale = (ph == 0 && cq < 2) ? 0.17677669529663687f : 1.0f;
    int colbase = cq * 64;
    int buf = 0;

    for (int mtile = slot; mtile < 2304; mtile += 148) {
        int mnext = mtile + 148;
        bool has_next = (mnext < 2304);

        uint2 pf[8];
        if (has_next) {
            int rsub = tid >> 5, col = (tid & 31) * 4;
            const __half* src = d_x + (size_t)(mnext * 64) * 128;
            #pragma unroll
            for (int j = 0; j < 8; j++)
                pf[j] = *(const uint2*)&src[(size_t)(j * 8 + rsub) * 128 + col];
        }

        const __half* Xs = Xb + buf * (64 * PJW);
        float c[16][4];
        #pragma unroll
        for (int i = 0; i < 16; i++)
            #pragma unroll
            for (int j = 0; j < 4; j++) c[i][j] = 0.f;

        int r0 = mhalf * 32;
        #pragma unroll
        for (int k16 = 0; k16 < 8; k16++) {
            int k0 = k16 * 16;
            unsigned a0 = *(const unsigned*)&Xs[(r0 + g) * PJW + k0 + 2*t];
            unsigned a1 = *(const unsigned*)&Xs[(r0 + 8 + g) * PJW + k0 + 2*t];
            unsigned a2 = *(const unsigned*)&Xs[(r0 + g) * PJW + k0 + 2*t + 8];
            unsigned a3 = *(const unsigned*)&Xs[(r0 + 8 + g) * PJW + k0 + 2*t + 8];
            unsigned a4 = *(const unsigned*)&Xs[(r0 + 16 + g) * PJW + k0 + 2*t];
            unsigned a5 = *(const unsigned*)&Xs[(r0 + 24 + g) * PJW + k0 + 2*t];
            unsigned a6 = *(const unsigned*)&Xs[(r0 + 16 + g) * PJW + k0 + 2*t + 8];
            unsigned a7 = *(const unsigned*)&Xs[(r0 + 24 + g) * PJW + k0 + 2*t + 8];
            #pragma unroll
            for (int nb = 0; nb < 8; nb++) {
                int n = colbase + nb * 8 + g;
                unsigned b0 = *(const unsigned*)&Wt[n * PJW + k0 + 2*t];
                unsigned b1 = *(const unsigned*)&Wt[n * PJW + k0 + 2*t + 8];
                mma_f16(c[nb][0], c[nb][1], c[nb][2], c[nb][3],
                        a0, a1, a2, a3, b0, b1);
                mma_f16(c[8+nb][0], c[8+nb][1], c[8+nb][2], c[8+nb][3],
                        a4, a5, a6, a7, b0, b1);
            }
        }

        {
            int r = mtile * 64 + mhalf * 32;
            #pragma unroll
            for (int nb = 0; nb < 8; nb++) {
                int col = ph * 256 + colbase + nb * 8 + 2 * t;
                *(unsigned*)&d_y[(size_t)(r + g) * 512 + col] =
                    h2u(c[nb][0] * scale, c[nb][1] * scale);
                *(unsigned*)&d_y[(size_t)(r + 8 + g) * 512 + col] =
                    h2u(c[nb][2] * scale, c[nb][3] * scale);
                *(unsigned*)&d_y[(size_t)(r + 16 + g) * 512 + col] =
                    h2u(c[8+nb][0] * scale, c[8+nb][1] * scale);
                *(unsigned*)&d_y[(size_t)(r + 24 + g) * 512 + col] =
                    h2u(c[8+nb][2] * scale, c[8+nb][3] * scale);
            }
        }

        __syncthreads();
        if (has_next) {
            __half* dst = Xb + (buf ^ 1) * (64 * PJW);
            int rsub = tid >> 5, col = (tid & 31) * 4;
            #pragma unroll
            for (int j = 0; j < 8; j++)
                *(uint2*)&dst[(j * 8 + rsub) * PJW + col] = pf[j];
        }
        __syncthreads();
        buf ^= 1;
    }
}

// ---------------------------------------------------------------------------
// Kernel 3: attention per (b,h), fp16 m16n8k16 flash. d_o stored fp16.
// ---------------------------------------------------------------------------
#define AKS 40
#define AVS 392
#define ATTN_SMEM_BYTES (384*AKS*2 + 32*AVS*2 + 384*4)

__global__ __launch_bounds__(256) void attn_fp16(const int* __restrict__ mask)
{
    extern __shared__ char asm_[];
    __half* Ks = (__half*)asm_;                     // [384][40]
    __half* Vt = Ks + 384 * AKS;                    // [32][392]
    float*  Am = (float*)(Vt + 32 * AVS);           // [384]

    int b = blockIdx.x, h = blockIdx.y;
    int tid = threadIdx.x, lane = tid & 31, w = tid >> 5;
    int g = lane >> 2, t = lane & 3;
    const __half* Yb = d_y + (size_t)b * (NN * 512);

    for (int idx = tid; idx < 384 * 8; idx += 256) {
        int key = idx >> 3, d4 = (idx & 7) * 4;
        uint2 v = *(const uint2*)&Yb[(size_t)key * 512 + 128 + h * 32 + d4];
        *(uint2*)&Ks[key * AKS + d4] = v;
    }
    for (int idx = tid; idx < 384 * 32; idx += 256) {
        int key = idx >> 5, d = idx & 31;
        Vt[d * AVS + key] = Yb[(size_t)key * 512 + 256 + h * 32 + d];
    }
    for (int k = tid; k < NN; k += 256)
        Am[k] = (mask[(size_t)b * NN + k] != 0) ? 0.f : -1e9f;
    __syncthreads();

    for (int mt = w; mt < 24; mt += 8) {
        int q0 = mt * 16;

        unsigned aq[2][4];
        #pragma unroll
        for (int s = 0; s < 2; s++) {
            int dc = h * 32 + 16 * s + 2 * t;
            aq[s][0] = *(const unsigned*)&Yb[(size_t)(q0 + g) * 512 + dc];
            aq[s][1] = *(const unsigned*)&Yb[(size_t)(q0 + 8 + g) * 512 + dc];
            aq[s][2] = *(const unsigned*)&Yb[(size_t)(q0 + g) * 512 + dc + 8];
            aq[s][3] = *(const unsigned*)&Yb[(size_t)(q0 + 8 + g) * 512 + dc + 8];
        }

        float oc[4][4];
        #pragma unroll
        for (int dn = 0; dn < 4; dn++)
            #pragma unroll
            for (int j = 0; j < 4; j++) oc[dn][j] = 0.f;
        float sum_lo = 0.f, sum_hi = 0.f;

        const float* br_lo = d_bias + (size_t)h * MM + (size_t)(q0 + g) * NN;
        const float* br_hi = br_lo + (size_t)8 * NN;

        for (int kb = 0; kb < 6; kb++) {
            float pc[8][4];

            #pragma unroll
            for (int nb = 0; nb < 8; nb++) {
                int k8 = kb * 64 + nb * 8;
                float c0 = 0.f, c1 = 0.f, c2 = 0.f, c3 = 0.f;
                #pragma unroll
                for (int s = 0; s < 2; s++) {
                    unsigned b0 = *(const unsigned*)&Ks[(k8 + g) * AKS + 16*s + 2*t];
                    unsigned b1 = *(const unsigned*)&Ks[(k8 + g) * AKS + 16*s + 2*t + 8];
                    mma_f16(c0, c1, c2, c3,
                            aq[s][0], aq[s][1], aq[s][2], aq[s][3], b0, b1);
                }
                int col = k8 + 2 * t;
                float2 blo = *(const float2*)&br_lo[col];
                float2 bhi = *(const float2*)&br_hi[col];
                float2 am  = *(const float2*)&Am[col];
                float e0 = __expf(c0 + blo.x + am.x);
                float e1 = __expf(c1 + blo.y + am.y);
                float e2 = __expf(c2 + bhi.x + am.x);
                float e3 = __expf(c3 + bhi.y + am.y);
                sum_lo += e0 + e1;
                sum_hi += e2 + e3;
                pc[nb][0] = e0; pc[nb][1] = e1; pc[nb][2] = e2; pc[nb][3] = e3;
            }

            #pragma unroll
            for (int j = 0; j < 4; j++) {
                unsigned a0 = h2u(pc[2*j][0],   pc[2*j][1]);
                unsigned a1 = h2u(pc[2*j][2],   pc[2*j][3]);
                unsigned a2 = h2u(pc[2*j+1][0], pc[2*j+1][1]);
                unsigned a3 = h2u(pc[2*j+1][2], pc[2*j+1][3]);
                int kg = kb * 64 + j * 16;
                #pragma unroll
                for (int dn = 0; dn < 4; dn++) {
                    unsigned b0 = *(const unsigned*)&Vt[(dn*8 + g) * AVS + kg + 2*t];
                    unsigned b1 = *(const unsigned*)&Vt[(dn*8 + g) * AVS + kg + 2*t + 8];
                    mma_f16(oc[dn][0], oc[dn][1], oc[dn][2], oc[dn][3],
                            a0, a1, a2, a3, b0, b1);
                }
            }
        }

        #pragma unroll
        for (int o = 1; o <= 2; o <<= 1) {
            sum_lo += __shfl_xor_sync(0xffffffffu, sum_lo, o);
            sum_hi += __shfl_xor_sync(0xffffffffu, sum_hi, o);
        }
        float inv_lo = 1.f / sum_lo;
        float inv_hi = 1.f / sum_hi;

        __half* ob = d_o + ((size_t)b * NN + q0) * CC + h * 32;
        #pragma unroll
        for (int dn = 0; dn < 4; dn++) {
            *(unsigned*)&ob[(size_t)g * CC + dn * 8 + 2 * t] =
                h2u(oc[dn][0] * inv_lo, oc[dn][1] * inv_lo);
            *(unsigned*)&ob[(size_t)(g + 8) * CC + dn * 8 + 2 * t] =
                h2u(oc[dn][2] * inv_hi, oc[dn][3] * inv_hi);
        }
    }
}

// ---------------------------------------------------------------------------
// Kernel 4: out = (o * sigmoid(g)) @ wo, persistent-W fp16 m16n8k16.
// d_o now fp16; gate from fp16 d_y fused into A staging.
// ---------------------------------------------------------------------------
#define OGW 136
#define OUT_SMEM_BYTES ((128*OGW + 64*OGW) * 2)

__global__ __launch_bounds__(256) void out_fp16(
    const float* __restrict__ wo, float* __restrict__ out)
{
    extern __shared__ char osm[];
    __half* Wh = (__half*)osm;            // [128][136]
    __half* Ah = Wh + 128 * OGW;          // [64][136]

    int tid = threadIdx.x, lane = tid & 31, warp = tid >> 5;
    int g = lane >> 2, t = lane & 3;
    int mhalf = warp >> 2;
    int cq = warp & 3;

    for (int i = tid; i < 128 * 128; i += 256) {
        int n = i & 127, k = i >> 7;
        Wh[n * OGW + k] = __float2half(wo[(size_t)k * 128 + n]);
    }

    for (int tile = blockIdx.x; tile < 2304; tile += 592) {
        int m0 = tile * 64;
        __syncthreads();
        for (int i = tid; i < 64 * 32; i += 256) {
            int row = i >> 5, c4 = (i & 31) * 4;
            uint2 ou = *(const uint2*)&d_o[(size_t)(m0 + row) * 128 + c4];
            uint2 gu = *(const uint2*)&d_y[(size_t)(m0 + row) * 512 + 384 + c4];
            float2 of01 = __half22float2(reinterpret_cast<__half2&>(ou.x));
            float2 of23 = __half22float2(reinterpret_cast<__half2&>(ou.y));
            float2 gf01 = __half22float2(reinterpret_cast<__half2&>(gu.x));
            float2 gf23 = __half22float2(reinterpret_cast<__half2&>(gu.y));
            float a0 = of01.x * (1.f / (1.f + __expf(-gf01.x)));
            float a1 = of01.y * (1.f / (1.f + __expf(-gf01.y)));
            float a2 = of23.x * (1.f / (1.f + __expf(-gf23.x)));
            float a3 = of23.y * (1.f / (1.f + __expf(-gf23.y)));
            uint2 o;
            o.x = h2u(a0, a1);
            o.y = h2u(a2, a3);
            *(uint2*)&Ah[row * OGW + c4] = o;
        }
        __syncthreads();

        float c[2][4][4];
        #pragma unroll
        for (int mm = 0; mm < 2; mm++)
            #pragma unroll
            for (int nb = 0; nb < 4; nb++)
                #pragma unroll
                for (int j = 0; j < 4; j++) c[mm][nb][j] = 0.f;

        #pragma unroll
        for (int k16 = 0; k16 < 8; k16++) {
            int k0 = k16 * 16;
            #pragma unroll
            for (int mm = 0; mm < 2; mm++) {
                int r0 = mhalf * 32 + mm * 16;
                unsigned a0 = *(const unsigned*)&Ah[(r0 + g) * OGW + k0 + 2*t];
                unsigned a1 = *(const unsigned*)&Ah[(r0 + 8 + g) * OGW + k0 + 2*t];
                unsigned a2 = *(const unsigned*)&Ah[(r0 + g) * OGW + k0 + 2*t + 8];
                unsigned a3 = *(const unsigned*)&Ah[(r0 + 8 + g) * OGW + k0 + 2*t + 8];
                #pragma unroll
                for (int nb = 0; nb < 4; nb++) {
                    int n = cq * 32 + nb * 8 + g;
                    unsigned b0 = *(const unsigned*)&Wh[n * OGW + k0 + 2*t];
                    unsigned b1 = *(const unsigned*)&Wh[n * OGW + k0 + 2*t + 8];
                    mma_f16(c[mm][nb][0], c[mm][nb][1], c[mm][nb][2], c[mm][nb][3],
                            a0, a1, a2, a3, b0, b1);
                }
            }
        }

        #pragma unroll
        for (int mm = 0; mm < 2; mm++) {
            int r = m0 + mhalf * 32 + mm * 16;
            #pragma unroll
            for (int nb = 0; nb < 4; nb++) {
                int col = cq * 32 + nb * 8 + 2 * t;
                *(float2*)&out[(size_t)(r + g) * 128 + col] =
                    make_float2(c[mm][nb][0], c[mm][nb][1]);
                *(float2*)&out[(size_t)(r + 8 + g) * 128 + col] =
                    make_float2(c[mm][nb][2], c[mm][nb][3]);
            }
        }
    }
}

// ---------------------------------------------------------------------------
extern "C" void kernel_launch(void* const* d_in, const int* in_sizes, int n_in,
                              void* d_out, int out_size)
{
    const float* pair   = (const float*)d_in[0];
    const int*   mask   = (const int*)d_in[1];
    const float* ln_w   = (const float*)d_in[2];
    const float* ln_b   = (const float*)d_in[3];
    const float* w_bias = (const float*)d_in[4];
    const float* wq     = (const float*)d_in[5];
    const float* wk     = (const float*)d_in[6];
    const float* wv     = (const float*)d_in[7];
    const float* wg     = (const float*)d_in[8];
    const float* wo     = (const float*)d_in[9];
    float* out = (float*)d_out;

    (void)in_sizes; (void)n_in; (void)out_size;

    ln_bias_kernel<<<MM / 8, 256>>>(pair, ln_w, ln_b, w_bias);

    cudaFuncSetAttribute(proj_fp16,
                         cudaFuncAttributeMaxDynamicSharedMemorySize, PROJ_SMEM_BYTES);
    proj_fp16<<<dim3(148, 2), 256, PROJ_SMEM_BYTES>>>(wq, wk, wv, wg);

    cudaFuncSetAttribute(attn_fp16,
                         cudaFuncAttributeMaxDynamicSharedMemorySize, ATTN_SMEM_BYTES);
    attn_fp16<<<dim3(NN, HH), 256, ATTN_SMEM_BYTES>>>(mask);

    cudaFuncSetAttribute(out_fp16,
                         cudaFuncAttributeMaxDynamicSharedMemorySize, OUT_SMEM_BYTES);
    out_fp16<<<592, 256, OUT_SMEM_BYTES>>>(wo, out);
}